// round 5
// baseline (speedup 1.0000x reference)
#include <cuda_runtime.h>
#include <cuda_bf16.h>
#include <math.h>

// Problem constants (match reference)
#define NN 50000
#define EE 1600000
#define FIN 256
#define HH 128
#define CC 40

// ---------------- device scratch (no allocs allowed) ----------------
__device__ __align__(16) float g_bufA[(size_t)NN * HH];
__device__ __align__(16) float g_bufB[(size_t)NN * HH];
__device__ float g_inv[NN];
__device__ int   g_deg[NN];
__device__ int   g_rowptr[NN + 1];
__device__ int   g_cursor[NN];
__device__ int   g_esrc[EE];
__device__ __align__(16) float g_ewt[EE];
__device__ float g_Wc[CC * CC];      // We @ Wf_top  (40x40)
__device__ float g_cbias[CC];        // bf + be @ Wf_top

// ---------------- row L2 norm (inverse, clamped) ----------------
__global__ void rownorm_kernel(const float* __restrict__ x, int n) {
    int w = (blockIdx.x * blockDim.x + threadIdx.x) >> 5;
    int lane = threadIdx.x & 31;
    if (w >= n) return;
    const float4* p = (const float4*)(x + (size_t)w * FIN);
    float4 a = p[lane];
    float4 b = p[lane + 32];
    float s = a.x*a.x + a.y*a.y + a.z*a.z + a.w*a.w
            + b.x*b.x + b.y*b.y + b.z*b.z + b.w*b.w;
    #pragma unroll
    for (int off = 16; off > 0; off >>= 1) s += __shfl_xor_sync(0xffffffffu, s, off);
    if (lane == 0) g_inv[w] = 1.0f / fmaxf(sqrtf(s), 1e-12f);
}

// ---------------- SGEMM (double buffered): C[M x 128] tile = A[M x K] * B[K x 128] ----------------
#define GBM 128
#define GBN 64
#define GBK 8
template<bool SCALE>
__global__ __launch_bounds__(256, 3) void gemm_kernel(
    const float* __restrict__ A, const float* __restrict__ B,
    float* __restrict__ C, int M, int K)
{
    __shared__ float As[2][GBK][GBM + 4];
    __shared__ float Bs[2][GBK][GBN];
    int tid = threadIdx.x;
    int m0 = blockIdx.x * GBM;
    int n0 = blockIdx.y * GBN;
    int tx = tid & 15, ty = tid >> 4;

    int arow = tid >> 1;
    int ahalf = (tid & 1) * 4;
    bool aok = (m0 + arow) < M;
    const float* Aptr = A + (size_t)(m0 + arow) * K + ahalf;
    int brow = tid >> 5;
    int bcol = (tid & 31) * 2;
    const float* Bptr = B + (size_t)brow * HH + n0 + bcol;

    float acc[8][4];
    #pragma unroll
    for (int i = 0; i < 8; i++)
        #pragma unroll
        for (int j = 0; j < 4; j++) acc[i][j] = 0.0f;

    float4 areg = make_float4(0.f, 0.f, 0.f, 0.f);
    if (aok) areg = *(const float4*)Aptr;
    float2 breg = *(const float2*)Bptr;

    As[0][ahalf + 0][arow] = areg.x;
    As[0][ahalf + 1][arow] = areg.y;
    As[0][ahalf + 2][arow] = areg.z;
    As[0][ahalf + 3][arow] = areg.w;
    Bs[0][brow][bcol] = breg.x;
    Bs[0][brow][bcol + 1] = breg.y;
    __syncthreads();

    int buf = 0;
    for (int k0 = GBK; k0 < K; k0 += GBK) {
        areg = make_float4(0.f, 0.f, 0.f, 0.f);
        if (aok) areg = *(const float4*)(Aptr + k0);
        breg = *(const float2*)(Bptr + (size_t)k0 * HH);

        #pragma unroll
        for (int kk = 0; kk < GBK; kk++) {
            float ra[8], rb[4];
            *(float4*)(ra)     = *(const float4*)&As[buf][kk][ty * 8];
            *(float4*)(ra + 4) = *(const float4*)&As[buf][kk][ty * 8 + 4];
            *(float4*)(rb)     = *(const float4*)&Bs[buf][kk][tx * 4];
            #pragma unroll
            for (int i = 0; i < 8; i++)
                #pragma unroll
                for (int j = 0; j < 4; j++) acc[i][j] += ra[i] * rb[j];
        }

        int nb = buf ^ 1;
        As[nb][ahalf + 0][arow] = areg.x;
        As[nb][ahalf + 1][arow] = areg.y;
        As[nb][ahalf + 2][arow] = areg.z;
        As[nb][ahalf + 3][arow] = areg.w;
        Bs[nb][brow][bcol] = breg.x;
        Bs[nb][brow][bcol + 1] = breg.y;
        __syncthreads();
        buf = nb;
    }
    #pragma unroll
    for (int kk = 0; kk < GBK; kk++) {
        float ra[8], rb[4];
        *(float4*)(ra)     = *(const float4*)&As[buf][kk][ty * 8];
        *(float4*)(ra + 4) = *(const float4*)&As[buf][kk][ty * 8 + 4];
        *(float4*)(rb)     = *(const float4*)&Bs[buf][kk][tx * 4];
        #pragma unroll
        for (int i = 0; i < 8; i++)
            #pragma unroll
            for (int j = 0; j < 4; j++) acc[i][j] += ra[i] * rb[j];
    }

    #pragma unroll
    for (int i = 0; i < 8; i++) {
        int gr = m0 + ty * 8 + i;
        if (gr >= M) continue;
        float s = SCALE ? g_inv[gr] : 1.0f;
        float4 v;
        v.x = acc[i][0] * s; v.y = acc[i][1] * s;
        v.z = acc[i][2] * s; v.w = acc[i][3] * s;
        *(float4*)(C + (size_t)gr * HH + n0 + tx * 4) = v;
    }
}

// ---------------- CSR build ----------------
__global__ void zero_deg_kernel(int n) {
    int i = blockIdx.x * blockDim.x + threadIdx.x;
    if (i < n) g_deg[i] = 0;
}
__global__ void hist_kernel(const int* __restrict__ dst, int e) {
    int i = blockIdx.x * blockDim.x + threadIdx.x;
    if (i < e) atomicAdd(&g_deg[dst[i]], 1);
}
__global__ void scan_kernel(int n) {
    __shared__ int wsum[32];
    __shared__ int s_run;
    int tid = threadIdx.x, lane = tid & 31, wid = tid >> 5;
    if (tid == 0) s_run = 0;
    __syncthreads();
    for (int base = 0; base < n; base += 1024) {
        int idx = base + tid;
        int v = (idx < n) ? g_deg[idx] : 0;
        int inc = v;
        #pragma unroll
        for (int off = 1; off < 32; off <<= 1) {
            int t = __shfl_up_sync(0xffffffffu, inc, off);
            if (lane >= off) inc += t;
        }
        if (lane == 31) wsum[wid] = inc;
        __syncthreads();
        if (wid == 0) {
            int x = wsum[lane];
            #pragma unroll
            for (int off = 1; off < 32; off <<= 1) {
                int t = __shfl_up_sync(0xffffffffu, x, off);
                if (lane >= off) x += t;
            }
            wsum[lane] = x;
        }
        __syncthreads();
        int woff = (wid > 0) ? wsum[wid - 1] : 0;
        int run = s_run;
        int excl = run + woff + inc - v;
        if (idx < n) { g_rowptr[idx] = excl; g_cursor[idx] = excl; }
        __syncthreads();
        if (tid == 0) s_run = run + wsum[31];
        __syncthreads();
    }
    if (threadIdx.x == 0) g_rowptr[n] = s_run;
}
__global__ void scatter_kernel(const int* __restrict__ src, const int* __restrict__ dst,
                               const float* __restrict__ w, int e) {
    int i = blockIdx.x * blockDim.x + threadIdx.x;
    if (i < e) {
        int d = dst[i];
        int pos = atomicAdd(&g_cursor[d], 1);
        g_esrc[pos] = src[i];
        g_ewt[pos]  = w[i];
    }
}

// ---------------- SPMM: CTA per row, thread per column ----------------
// out[row][t] = bias[t] + sum_e w_e * x[src_e][t]; per-edge load is one
// coalesced 128B line per warp; edge (src,w) staged via shared broadcast.
template<bool RELU>
__global__ __launch_bounds__(128) void spmm_kernel(
    const float* __restrict__ x, float* __restrict__ out,
    const float* __restrict__ bias, int n)
{
    __shared__ int   s_src[64];
    __shared__ float s_wt[64];
    int row = blockIdx.x;
    if (row >= n) return;
    int tid = threadIdx.x;
    int e0 = g_rowptr[row], e1 = g_rowptr[row + 1];
    float acc = bias[tid];

    for (int base = e0; base < e1; base += 64) {
        int cnt = min(64, e1 - base);
        __syncthreads();
        if (tid < cnt) {
            s_src[tid] = g_esrc[base + tid];
            s_wt[tid]  = g_ewt[base + tid];
        }
        __syncthreads();
        int j = 0;
        for (; j + 8 <= cnt; j += 8) {
            int   i0 = s_src[j],     i1 = s_src[j + 1], i2 = s_src[j + 2], i3 = s_src[j + 3];
            int   i4 = s_src[j + 4], i5 = s_src[j + 5], i6 = s_src[j + 6], i7 = s_src[j + 7];
            float v0 = x[(size_t)i0 * HH + tid];
            float v1 = x[(size_t)i1 * HH + tid];
            float v2 = x[(size_t)i2 * HH + tid];
            float v3 = x[(size_t)i3 * HH + tid];
            float v4 = x[(size_t)i4 * HH + tid];
            float v5 = x[(size_t)i5 * HH + tid];
            float v6 = x[(size_t)i6 * HH + tid];
            float v7 = x[(size_t)i7 * HH + tid];
            acc += s_wt[j]     * v0;
            acc += s_wt[j + 1] * v1;
            acc += s_wt[j + 2] * v2;
            acc += s_wt[j + 3] * v3;
            acc += s_wt[j + 4] * v4;
            acc += s_wt[j + 5] * v5;
            acc += s_wt[j + 6] * v6;
            acc += s_wt[j + 7] * v7;
        }
        for (; j < cnt; j++) {
            acc += s_wt[j] * x[(size_t)s_src[j] * HH + tid];
        }
    }
    if (RELU) acc = fmaxf(acc, 0.f);
    out[(size_t)row * HH + tid] = acc;
}

// ---------------- head weight pre-combine ----------------
__global__ void wcomb_kernel(const float* __restrict__ We, const float* __restrict__ be,
                             const float* __restrict__ Wf, const float* __restrict__ bf)
{
    int t = blockIdx.x * blockDim.x + threadIdx.x;
    if (t < CC * CC) {
        int i = t / CC, c = t % CC;
        float s = 0.f;
        for (int k = 0; k < HH; k++) s += We[i * HH + k] * Wf[k * CC + c];
        g_Wc[t] = s;
    }
    if (t < CC) {
        float s = bf[t];
        for (int k = 0; k < HH; k++) s += be[k] * Wf[k * CC + t];
        g_cbias[t] = s;
    }
}

// ---------------- fused head: logits = y@Wc + h@Wf_bot + cbias ; softmax ----------------
__global__ __launch_bounds__(128) void head_kernel(
    const float* __restrict__ h, const float* __restrict__ yin,
    const float* __restrict__ Wf, float* __restrict__ out, int n)
{
    __shared__ float sWfb[HH * CC];
    __shared__ float sWc[CC * CC];
    __shared__ float sh[32 * HH];
    __shared__ float sl[32 * CC];
    __shared__ float smax[32], sinv[32];
    int tid = threadIdx.x;
    int r0 = blockIdx.x * 32;
    int rows = min(32, n - r0);

    for (int i = tid; i < HH * CC; i += 128) sWfb[i] = Wf[HH * CC + i];
    for (int i = tid; i < CC * CC; i += 128) sWc[i] = g_Wc[i];
    for (int i = tid; i < rows * HH; i += 128) sh[i] = h[(size_t)r0 * HH + i];
    __syncthreads();

    int r = tid >> 2, q = tid & 3, c0 = q * 10;
    if (r < rows) {
        float acc[10];
        #pragma unroll
        for (int j = 0; j < 10; j++) acc[j] = g_cbias[c0 + j];
        for (int k = 0; k < HH; k++) {
            float hv = sh[r * HH + k];
            #pragma unroll
            for (int j = 0; j < 10; j++) acc[j] += hv * sWfb[k * CC + c0 + j];
        }
        const float* yr = yin + (size_t)(r0 + r) * CC;
        for (int k = 0; k < CC; k++) {
            float yv = yr[k];
            #pragma unroll
            for (int j = 0; j < 10; j++) acc[j] += yv * sWc[k * CC + c0 + j];
        }
        #pragma unroll
        for (int j = 0; j < 10; j++) sl[r * CC + c0 + j] = acc[j];
    }
    __syncthreads();
    if (tid < 32 && tid < rows) {
        float m = -1e30f;
        for (int c = 0; c < CC; c++) m = fmaxf(m, sl[tid * CC + c]);
        float s = 0.f;
        for (int c = 0; c < CC; c++) s += __expf(sl[tid * CC + c] - m);
        smax[tid] = m;
        sinv[tid] = 1.0f / s;
    }
    __syncthreads();
    int tot = rows * CC;
    for (int i = tid; i < tot; i += 128) {
        int rr = i / CC;
        out[(size_t)r0 * CC + i] = __expf(sl[i] - smax[rr]) * sinv[rr];
    }
}

// ---------------- launch ----------------
extern "C" void kernel_launch(void* const* d_in, const int* in_sizes, int n_in,
                              void* d_out, int out_size)
{
    const float* features = (const float*)d_in[0];
    const int*   src      = (const int*)  d_in[1];
    const int*   dst      = (const int*)  d_in[2];
    const float* ew       = (const float*)d_in[3];
    const float* y        = (const float*)d_in[4];
    const float* W1       = (const float*)d_in[5];
    const float* b1       = (const float*)d_in[6];
    const float* W2       = (const float*)d_in[7];
    const float* b2       = (const float*)d_in[8];
    const float* We       = (const float*)d_in[9];
    const float* be       = (const float*)d_in[10];
    const float* Wf       = (const float*)d_in[11];
    const float* bf       = (const float*)d_in[12];
    float* out = (float*)d_out;

    int n = in_sizes[0] / FIN;     // 50000
    int e = in_sizes[1];           // 1600000

    int warpBlocks = (n + 7) / 8;
    int edgeBlocks = (e + 255) / 256;
    dim3 gemmGrid((n + GBM - 1) / GBM, HH / GBN);

    zero_deg_kernel<<<(n + 255) / 256, 256>>>(n);                      // 1
    hist_kernel<<<edgeBlocks, 256>>>(dst, e);                          // 2
    scan_kernel<<<1, 1024>>>(n);                                       // 3
    // PROBE (profiled slot 4): duplicate spmm<true>. Reads device-global state
    // that is identical on every call after the first (CSR arrays + g_bufA are
    // recomputed to the same values each call); its g_bufB output is
    // overwritten by the real spmm below before any consumer reads it.
    spmm_kernel<true><<<n, 128>>>(g_bufA, g_bufB, b1, n);              // 4  <-- profiled
    scatter_kernel<<<edgeBlocks, 256>>>(src, dst, ew, e);              // 5
    rownorm_kernel<<<warpBlocks, 256>>>(features, n);                  // 6
    gemm_kernel<true><<<gemmGrid, 256>>>(features, W1, g_bufA, n, FIN);// 7

    spmm_kernel<true><<<n, 128>>>(g_bufA, g_bufB, b1, n);              // 8
    gemm_kernel<false><<<gemmGrid, 256>>>(g_bufB, W2, g_bufA, n, HH);  // 9
    spmm_kernel<false><<<n, 128>>>(g_bufA, g_bufB, b2, n);             // 10

    wcomb_kernel<<<7, 256>>>(We, be, Wf, bf);                          // 11
    head_kernel<<<(n + 31) / 32, 128>>>(g_bufB, y, Wf, out, n);        // 12
}

// round 7
// speedup vs baseline: 1.0514x; 1.0514x over previous
#include <cuda_runtime.h>
#include <cuda_bf16.h>
#include <math.h>

// Problem constants (match reference)
#define NN 50000
#define EE 1600000
#define FIN 256
#define HH 128
#define CC 40

// ---------------- device scratch (no allocs allowed) ----------------
__device__ __align__(16) float g_bufA[(size_t)NN * HH];
__device__ __align__(16) float g_bufB[(size_t)NN * HH];
__device__ float g_inv[NN];
__device__ int   g_deg[NN];          // zero-init at load; scan re-zeroes after use
__device__ int   g_rowptr[NN + 1];
__device__ int   g_cursor[NN];
__device__ int   g_esrc[EE];
__device__ __align__(16) float g_ewt[EE];
__device__ float g_Wc[CC * CC];
__device__ float g_cbias[CC];

// ---------------- row L2 norm (inverse, clamped) ----------------
__global__ void rownorm_kernel(const float* __restrict__ x, int n) {
    int w = (blockIdx.x * blockDim.x + threadIdx.x) >> 5;
    int lane = threadIdx.x & 31;
    if (w >= n) return;
    const float4* p = (const float4*)(x + (size_t)w * FIN);
    float4 a = p[lane];
    float4 b = p[lane + 32];
    float s = a.x*a.x + a.y*a.y + a.z*a.z + a.w*a.w
            + b.x*b.x + b.y*b.y + b.z*b.z + b.w*b.w;
    #pragma unroll
    for (int off = 16; off > 0; off >>= 1) s += __shfl_xor_sync(0xffffffffu, s, off);
    if (lane == 0) g_inv[w] = 1.0f / fmaxf(sqrtf(s), 1e-12f);
}

// ---------------- SGEMM (double buffered) ----------------
#define GBM 128
#define GBN 64
#define GBK 8
template<bool SCALE>
__global__ __launch_bounds__(256, 3) void gemm_kernel(
    const float* __restrict__ A, const float* __restrict__ B,
    float* __restrict__ C, int M, int K)
{
    __shared__ float As[2][GBK][GBM + 4];
    __shared__ float Bs[2][GBK][GBN];
    int tid = threadIdx.x;
    int m0 = blockIdx.x * GBM;
    int n0 = blockIdx.y * GBN;
    int tx = tid & 15, ty = tid >> 4;

    int arow = tid >> 1;
    int ahalf = (tid & 1) * 4;
    bool aok = (m0 + arow) < M;
    const float* Aptr = A + (size_t)(m0 + arow) * K + ahalf;
    int brow = tid >> 5;
    int bcol = (tid & 31) * 2;
    const float* Bptr = B + (size_t)brow * HH + n0 + bcol;

    float acc[8][4];
    #pragma unroll
    for (int i = 0; i < 8; i++)
        #pragma unroll
        for (int j = 0; j < 4; j++) acc[i][j] = 0.0f;

    float4 areg = make_float4(0.f, 0.f, 0.f, 0.f);
    if (aok) areg = *(const float4*)Aptr;
    float2 breg = *(const float2*)Bptr;

    As[0][ahalf + 0][arow] = areg.x;
    As[0][ahalf + 1][arow] = areg.y;
    As[0][ahalf + 2][arow] = areg.z;
    As[0][ahalf + 3][arow] = areg.w;
    Bs[0][brow][bcol] = breg.x;
    Bs[0][brow][bcol + 1] = breg.y;
    __syncthreads();

    int buf = 0;
    for (int k0 = GBK; k0 < K; k0 += GBK) {
        areg = make_float4(0.f, 0.f, 0.f, 0.f);
        if (aok) areg = *(const float4*)(Aptr + k0);
        breg = *(const float2*)(Bptr + (size_t)k0 * HH);

        #pragma unroll
        for (int kk = 0; kk < GBK; kk++) {
            float ra[8], rb[4];
            *(float4*)(ra)     = *(const float4*)&As[buf][kk][ty * 8];
            *(float4*)(ra + 4) = *(const float4*)&As[buf][kk][ty * 8 + 4];
            *(float4*)(rb)     = *(const float4*)&Bs[buf][kk][tx * 4];
            #pragma unroll
            for (int i = 0; i < 8; i++)
                #pragma unroll
                for (int j = 0; j < 4; j++) acc[i][j] += ra[i] * rb[j];
        }

        int nb = buf ^ 1;
        As[nb][ahalf + 0][arow] = areg.x;
        As[nb][ahalf + 1][arow] = areg.y;
        As[nb][ahalf + 2][arow] = areg.z;
        As[nb][ahalf + 3][arow] = areg.w;
        Bs[nb][brow][bcol] = breg.x;
        Bs[nb][brow][bcol + 1] = breg.y;
        __syncthreads();
        buf = nb;
    }
    #pragma unroll
    for (int kk = 0; kk < GBK; kk++) {
        float ra[8], rb[4];
        *(float4*)(ra)     = *(const float4*)&As[buf][kk][ty * 8];
        *(float4*)(ra + 4) = *(const float4*)&As[buf][kk][ty * 8 + 4];
        *(float4*)(rb)     = *(const float4*)&Bs[buf][kk][tx * 4];
        #pragma unroll
        for (int i = 0; i < 8; i++)
            #pragma unroll
            for (int j = 0; j < 4; j++) acc[i][j] += ra[i] * rb[j];
    }

    #pragma unroll
    for (int i = 0; i < 8; i++) {
        int gr = m0 + ty * 8 + i;
        if (gr >= M) continue;
        float s = SCALE ? g_inv[gr] : 1.0f;
        float4 v;
        v.x = acc[i][0] * s; v.y = acc[i][1] * s;
        v.z = acc[i][2] * s; v.w = acc[i][3] * s;
        *(float4*)(C + (size_t)gr * HH + n0 + tx * 4) = v;
    }
}

// ---------------- CSR build ----------------
__global__ void hist_kernel(const int* __restrict__ dst, int e) {
    int i = blockIdx.x * blockDim.x + threadIdx.x;
    if (i < e) atomicAdd(&g_deg[dst[i]], 1);
}
// scan + re-zero g_deg (so no separate zero pass is needed next call)
__global__ void scan_kernel(int n) {
    __shared__ int wsum[32];
    __shared__ int s_run;
    int tid = threadIdx.x, lane = tid & 31, wid = tid >> 5;
    if (tid == 0) s_run = 0;
    __syncthreads();
    for (int base = 0; base < n; base += 1024) {
        int idx = base + tid;
        int v = 0;
        if (idx < n) { v = g_deg[idx]; g_deg[idx] = 0; }
        int inc = v;
        #pragma unroll
        for (int off = 1; off < 32; off <<= 1) {
            int t = __shfl_up_sync(0xffffffffu, inc, off);
            if (lane >= off) inc += t;
        }
        if (lane == 31) wsum[wid] = inc;
        __syncthreads();
        if (wid == 0) {
            int x = wsum[lane];
            #pragma unroll
            for (int off = 1; off < 32; off <<= 1) {
                int t = __shfl_up_sync(0xffffffffu, x, off);
                if (lane >= off) x += t;
            }
            wsum[lane] = x;
        }
        __syncthreads();
        int woff = (wid > 0) ? wsum[wid - 1] : 0;
        int run = s_run;
        int excl = run + woff + inc - v;
        if (idx < n) { g_rowptr[idx] = excl; g_cursor[idx] = excl; }
        __syncthreads();
        if (tid == 0) s_run = run + wsum[31];
        __syncthreads();
    }
    if (threadIdx.x == 0) g_rowptr[n] = s_run;
}
__global__ void scatter_kernel(const int* __restrict__ src, const int* __restrict__ dst,
                               const float* __restrict__ w, int e) {
    int i = blockIdx.x * blockDim.x + threadIdx.x;
    if (i < e) {
        int d = dst[i];
        int pos = atomicAdd(&g_cursor[d], 1);
        g_esrc[pos] = src[i];
        g_ewt[pos]  = w[i];
    }
}

// ---------------- SPMM: CTA per row, thread per column, 16-deep MLP ----------------
template<bool RELU>
__global__ __launch_bounds__(128) void spmm_kernel(
    const float* __restrict__ x, float* __restrict__ out,
    const float* __restrict__ bias, int n)
{
    __shared__ int   s_src[64];
    __shared__ float s_wt[64];
    int row = blockIdx.x;
    if (row >= n) return;
    int tid = threadIdx.x;
    int e0 = g_rowptr[row], e1 = g_rowptr[row + 1];
    float acc = bias[tid];

    for (int base = e0; base < e1; base += 64) {
        int cnt = min(64, e1 - base);
        __syncthreads();
        if (tid < cnt) {
            s_src[tid] = g_esrc[base + tid];
            s_wt[tid]  = g_ewt[base + tid];
        }
        __syncthreads();
        int j = 0;
        for (; j + 16 <= cnt; j += 16) {
            int   ii[16];
            float vv[16];
            #pragma unroll
            for (int u = 0; u < 16; u++) ii[u] = s_src[j + u];
            #pragma unroll
            for (int u = 0; u < 16; u++) vv[u] = x[(size_t)ii[u] * HH + tid];
            #pragma unroll
            for (int u = 0; u < 16; u++) acc += s_wt[j + u] * vv[u];
        }
        for (; j + 4 <= cnt; j += 4) {
            int   i0 = s_src[j], i1 = s_src[j + 1], i2 = s_src[j + 2], i3 = s_src[j + 3];
            float v0 = x[(size_t)i0 * HH + tid];
            float v1 = x[(size_t)i1 * HH + tid];
            float v2 = x[(size_t)i2 * HH + tid];
            float v3 = x[(size_t)i3 * HH + tid];
            acc += s_wt[j]     * v0;
            acc += s_wt[j + 1] * v1;
            acc += s_wt[j + 2] * v2;
            acc += s_wt[j + 3] * v3;
        }
        for (; j < cnt; j++) {
            acc += s_wt[j] * x[(size_t)s_src[j] * HH + tid];
        }
    }
    if (RELU) acc = fmaxf(acc, 0.f);
    out[(size_t)row * HH + tid] = acc;
}

// ---------------- head weight pre-combine ----------------
__global__ void wcomb_kernel(const float* __restrict__ We, const float* __restrict__ be,
                             const float* __restrict__ Wf, const float* __restrict__ bf)
{
    int t = blockIdx.x * blockDim.x + threadIdx.x;
    if (t < CC * CC) {
        int i = t / CC, c = t % CC;
        float s = 0.f;
        for (int k = 0; k < HH; k++) s += We[i * HH + k] * Wf[k * CC + c];
        g_Wc[t] = s;
    }
    if (t < CC) {
        float s = bf[t];
        for (int k = 0; k < HH; k++) s += be[k] * Wf[k * CC + t];
        g_cbias[t] = s;
    }
}

// ---------------- fused head: logits = y@Wc + h@Wf_bot + cbias ; softmax ----------------
__global__ __launch_bounds__(128) void head_kernel(
    const float* __restrict__ h, const float* __restrict__ yin,
    const float* __restrict__ Wf, float* __restrict__ out, int n)
{
    __shared__ float sWfb[HH * CC];
    __shared__ float sWc[CC * CC];
    __shared__ float sh[32 * HH];
    __shared__ float sl[32 * CC];
    __shared__ float smax[32], sinv[32];
    int tid = threadIdx.x;
    int r0 = blockIdx.x * 32;
    int rows = min(32, n - r0);

    for (int i = tid; i < HH * CC; i += 128) sWfb[i] = Wf[HH * CC + i];
    for (int i = tid; i < CC * CC; i += 128) sWc[i] = g_Wc[i];
    for (int i = tid; i < rows * HH; i += 128) sh[i] = h[(size_t)r0 * HH + i];
    __syncthreads();

    int r = tid >> 2, q = tid & 3, c0 = q * 10;
    if (r < rows) {
        float acc[10];
        #pragma unroll
        for (int j = 0; j < 10; j++) acc[j] = g_cbias[c0 + j];
        for (int k = 0; k < HH; k++) {
            float hv = sh[r * HH + k];
            #pragma unroll
            for (int j = 0; j < 10; j++) acc[j] += hv * sWfb[k * CC + c0 + j];
        }
        const float* yr = yin + (size_t)(r0 + r) * CC;
        for (int k = 0; k < CC; k++) {
            float yv = yr[k];
            #pragma unroll
            for (int j = 0; j < 10; j++) acc[j] += yv * sWc[k * CC + c0 + j];
        }
        #pragma unroll
        for (int j = 0; j < 10; j++) sl[r * CC + c0 + j] = acc[j];
    }
    __syncthreads();
    if (tid < 32 && tid < rows) {
        float m = -1e30f;
        for (int c = 0; c < CC; c++) m = fmaxf(m, sl[tid * CC + c]);
        float s = 0.f;
        for (int c = 0; c < CC; c++) s += __expf(sl[tid * CC + c] - m);
        smax[tid] = m;
        sinv[tid] = 1.0f / s;
    }
    __syncthreads();
    int tot = rows * CC;
    for (int i = tid; i < tot; i += 128) {
        int rr = i / CC;
        out[(size_t)r0 * CC + i] = __expf(sl[i] - smax[rr]) * sinv[rr];
    }
}

// ---------------- launch ----------------
extern "C" void kernel_launch(void* const* d_in, const int* in_sizes, int n_in,
                              void* d_out, int out_size)
{
    const float* features = (const float*)d_in[0];
    const int*   src      = (const int*)  d_in[1];
    const int*   dst      = (const int*)  d_in[2];
    const float* ew       = (const float*)d_in[3];
    const float* y        = (const float*)d_in[4];
    const float* W1       = (const float*)d_in[5];
    const float* b1       = (const float*)d_in[6];
    const float* W2       = (const float*)d_in[7];
    const float* b2       = (const float*)d_in[8];
    const float* We       = (const float*)d_in[9];
    const float* be       = (const float*)d_in[10];
    const float* Wf       = (const float*)d_in[11];
    const float* bf       = (const float*)d_in[12];
    float* out = (float*)d_out;

    int n = in_sizes[0] / FIN;     // 50000
    int e = in_sizes[1];           // 1600000

    int warpBlocks = (n + 7) / 8;
    int edgeBlocks = (e + 255) / 256;
    dim3 gemmGrid((n + GBM - 1) / GBM, HH / GBN);

    hist_kernel<<<edgeBlocks, 256>>>(dst, e);                          // 1
    scan_kernel<<<1, 1024>>>(n);                                       // 2 (also zeroes g_deg)
    scatter_kernel<<<edgeBlocks, 256>>>(src, dst, ew, e);              // 3
    // PROBE (profiled slot 4): spmm with FULLY VALID CSR (scatter done above).
    // g_bufA values are zeros on call 1 / stale on replays — addresses (the
    // perf-relevant part) are the real random gather. Output g_bufB is
    // overwritten by the real spmm at slot 7 before any consumer reads it.
    spmm_kernel<true><<<n, 128>>>(g_bufA, g_bufB, b1, n);              // 4  <-- profiled (REAL pattern)
    rownorm_kernel<<<warpBlocks, 256>>>(features, n);                  // 5
    gemm_kernel<true><<<gemmGrid, 256>>>(features, W1, g_bufA, n, FIN);// 6

    spmm_kernel<true><<<n, 128>>>(g_bufA, g_bufB, b1, n);              // 7
    gemm_kernel<false><<<gemmGrid, 256>>>(g_bufB, W2, g_bufA, n, HH);  // 8
    spmm_kernel<false><<<n, 128>>>(g_bufA, g_bufB, b2, n);             // 9

    wcomb_kernel<<<7, 256>>>(We, be, Wf, bf);                          // 10
    head_kernel<<<(n + 31) / 32, 128>>>(g_bufB, y, Wf, out, n);        // 11
}

// round 8
// speedup vs baseline: 3.6439x; 3.4657x over previous
#include <cuda_runtime.h>
#include <cuda_bf16.h>
#include <math.h>

// Problem constants (match reference)
#define NN 50000
#define EE 1600000
#define FIN 256
#define HH 128
#define CC 40
#define NP 50048            // NN padded to multiple of 128 (pad rows stay 0)

// ---------------- device scratch (no allocs allowed) ----------------
__device__ __align__(16) float g_xT[(size_t)HH * NP];  // feature-major buffer A
__device__ __align__(16) float g_hT[(size_t)HH * NP];  // feature-major buffer B
__device__ int   g_deg[NN];           // zero at load; scan re-zeroes after use
__device__ int   g_rowptr[NN + 1];
__device__ int   g_cursor[NN];
__device__ __align__(16) int2 g_edge[EE];   // (src, float_bits(w)) sorted by dst
__device__ float g_Wc[CC * CC];
__device__ float g_cbias[CC];

// ---------------- CSR build ----------------
__global__ void hist_kernel(const int* __restrict__ dst, int e) {
    int i = blockIdx.x * blockDim.x + threadIdx.x;
    if (i < e) atomicAdd(&g_deg[dst[i]], 1);
}
__global__ void scan_kernel(int n) {
    __shared__ int wsum[32];
    __shared__ int s_run;
    int tid = threadIdx.x, lane = tid & 31, wid = tid >> 5;
    if (tid == 0) s_run = 0;
    __syncthreads();
    for (int base = 0; base < n; base += 1024) {
        int idx = base + tid;
        int v = 0;
        if (idx < n) { v = g_deg[idx]; g_deg[idx] = 0; }
        int inc = v;
        #pragma unroll
        for (int off = 1; off < 32; off <<= 1) {
            int t = __shfl_up_sync(0xffffffffu, inc, off);
            if (lane >= off) inc += t;
        }
        if (lane == 31) wsum[wid] = inc;
        __syncthreads();
        if (wid == 0) {
            int x = wsum[lane];
            #pragma unroll
            for (int off = 1; off < 32; off <<= 1) {
                int t = __shfl_up_sync(0xffffffffu, x, off);
                if (lane >= off) x += t;
            }
            wsum[lane] = x;
        }
        __syncthreads();
        int woff = (wid > 0) ? wsum[wid - 1] : 0;
        int run = s_run;
        int excl = run + woff + inc - v;
        if (idx < n) { g_rowptr[idx] = excl; g_cursor[idx] = excl; }
        __syncthreads();
        if (tid == 0) s_run = run + wsum[31];
        __syncthreads();
    }
    if (threadIdx.x == 0) g_rowptr[n] = s_run;
}
__global__ void scatter_kernel(const int* __restrict__ src, const int* __restrict__ dst,
                               const float* __restrict__ w, int e) {
    int i = blockIdx.x * blockDim.x + threadIdx.x;
    if (i < e) {
        int d = dst[i];
        int pos = atomicAdd(&g_cursor[d], 1);
        g_edge[pos] = make_int2(src[i], __float_as_int(w[i]));
    }
}

// ---------------- GEMM with transposed (feature-major) output ----------------
// C_T[n0+c][m0+r] = sum_k A[m][k]*B[k][n].  NORM: A node-major + fused L2-row-norm.
// AFM: A itself is feature-major (A_T[k][m]).
#define GBM 128
#define GBN 64
#define GBK 8
template<bool NORM, bool AFM>
__global__ __launch_bounds__(256, 3) void gemmT_kernel(
    const float* __restrict__ A, const float* __restrict__ B,
    float* __restrict__ CT, int M, int K)
{
    __shared__ float As[2][GBK][GBM + 4];
    __shared__ float Bs[2][GBK][GBN];
    __shared__ float sT[GBN][GBM + 1];
    __shared__ float s_invs[GBM];
    int tid = threadIdx.x;
    int m0 = blockIdx.x * GBM;
    int n0 = blockIdx.y * GBN;
    int tx = tid & 15, ty = tid >> 4;

    // node-major A loader: thread -> (row, 4-col half)
    int arow = tid >> 1;
    int ahalf = (tid & 1) * 4;
    bool aok = (m0 + arow) < M;
    const float* Aptr = A + (size_t)(m0 + arow) * K + ahalf;
    // f-major A loader: thread -> (k within tile, 4 cols of m)
    int akk = tid >> 5;
    int ac4 = (tid & 31) * 4;
    const float* AptrF = A + (size_t)akk * NP + m0 + ac4;
    // B loader
    int brow = tid >> 5;
    int bcol = (tid & 31) * 2;
    const float* Bptr = B + (size_t)brow * HH + n0 + bcol;

    float acc[8][4];
    #pragma unroll
    for (int i = 0; i < 8; i++)
        #pragma unroll
        for (int j = 0; j < 4; j++) acc[i][j] = 0.0f;
    float ssq = 0.0f;

    float4 areg;
    if (AFM) {
        areg = *(const float4*)AptrF;
    } else {
        areg = make_float4(0.f, 0.f, 0.f, 0.f);
        if (aok) areg = *(const float4*)Aptr;
        if (NORM) ssq += areg.x*areg.x + areg.y*areg.y + areg.z*areg.z + areg.w*areg.w;
    }
    float2 breg = *(const float2*)Bptr;

    if (AFM) {
        *(float4*)&As[0][akk][ac4] = areg;
    } else {
        As[0][ahalf + 0][arow] = areg.x;
        As[0][ahalf + 1][arow] = areg.y;
        As[0][ahalf + 2][arow] = areg.z;
        As[0][ahalf + 3][arow] = areg.w;
    }
    Bs[0][brow][bcol] = breg.x;
    Bs[0][brow][bcol + 1] = breg.y;
    __syncthreads();

    int buf = 0;
    for (int k0 = GBK; k0 < K; k0 += GBK) {
        if (AFM) {
            areg = *(const float4*)(AptrF + (size_t)k0 * NP);
        } else {
            areg = make_float4(0.f, 0.f, 0.f, 0.f);
            if (aok) areg = *(const float4*)(Aptr + k0);
            if (NORM) ssq += areg.x*areg.x + areg.y*areg.y + areg.z*areg.z + areg.w*areg.w;
        }
        breg = *(const float2*)(Bptr + (size_t)k0 * HH);

        #pragma unroll
        for (int kk = 0; kk < GBK; kk++) {
            float ra[8], rb[4];
            *(float4*)(ra)     = *(const float4*)&As[buf][kk][ty * 8];
            *(float4*)(ra + 4) = *(const float4*)&As[buf][kk][ty * 8 + 4];
            *(float4*)(rb)     = *(const float4*)&Bs[buf][kk][tx * 4];
            #pragma unroll
            for (int i = 0; i < 8; i++)
                #pragma unroll
                for (int j = 0; j < 4; j++) acc[i][j] += ra[i] * rb[j];
        }
        int nb = buf ^ 1;
        if (AFM) {
            *(float4*)&As[nb][akk][ac4] = areg;
        } else {
            As[nb][ahalf + 0][arow] = areg.x;
            As[nb][ahalf + 1][arow] = areg.y;
            As[nb][ahalf + 2][arow] = areg.z;
            As[nb][ahalf + 3][arow] = areg.w;
        }
        Bs[nb][brow][bcol] = breg.x;
        Bs[nb][brow][bcol + 1] = breg.y;
        __syncthreads();
        buf = nb;
    }
    #pragma unroll
    for (int kk = 0; kk < GBK; kk++) {
        float ra[8], rb[4];
        *(float4*)(ra)     = *(const float4*)&As[buf][kk][ty * 8];
        *(float4*)(ra + 4) = *(const float4*)&As[buf][kk][ty * 8 + 4];
        *(float4*)(rb)     = *(const float4*)&Bs[buf][kk][tx * 4];
        #pragma unroll
        for (int i = 0; i < 8; i++)
            #pragma unroll
            for (int j = 0; j < 4; j++) acc[i][j] += ra[i] * rb[j];
    }

    if (NORM) {
        float tot = ssq + __shfl_xor_sync(0xffffffffu, ssq, 1);
        s_invs[arow] = 1.0f / fmaxf(sqrtf(tot), 1e-12f);   // both pair lanes write same value
    }
    __syncthreads();

    // stage transposed tile
    #pragma unroll
    for (int i = 0; i < 8; i++) {
        float s = NORM ? s_invs[ty * 8 + i] : 1.0f;
        #pragma unroll
        for (int j = 0; j < 4; j++) sT[tx * 4 + j][ty * 8 + i] = acc[i][j] * s;
    }
    __syncthreads();
    // coalesced transposed writeout
    #pragma unroll
    for (int t = 0; t < 32; t++) {
        int lin = tid + t * 256;
        int c = lin >> 7;
        int r = lin & 127;
        int gr = m0 + r;
        if (gr < M) CT[(size_t)(n0 + c) * NP + gr] = sT[c][r];
    }
}

// ---------------- feature-major SPMM: one CTA per feature ----------------
// outT[f][row] = bias[f] + sum_{e in row} w_e * sx[src_e], sx = xT[f][:] in smem.
template<bool RELU>
__global__ void spmmT_kernel(const float* __restrict__ xT, float* __restrict__ outT,
                             const float* __restrict__ bias, int n)
{
    extern __shared__ float sx[];
    int f = blockIdx.x;
    const float* xrow = xT + (size_t)f * NP;
    for (int i = threadIdx.x; i < n; i += blockDim.x) sx[i] = xrow[i];
    __syncthreads();
    float b = bias[f];
    float* orow = outT + (size_t)f * NP;

    for (int row = threadIdx.x; row < n; row += blockDim.x) {
        int e0 = g_rowptr[row], e1 = g_rowptr[row + 1];
        float acc = b;
        int e = e0;
        for (; e + 4 <= e1; e += 4) {
            int2 d0 = g_edge[e], d1 = g_edge[e + 1], d2 = g_edge[e + 2], d3 = g_edge[e + 3];
            float v0 = sx[d0.x], v1 = sx[d1.x], v2 = sx[d2.x], v3 = sx[d3.x];
            acc += __int_as_float(d0.y) * v0;
            acc += __int_as_float(d1.y) * v1;
            acc += __int_as_float(d2.y) * v2;
            acc += __int_as_float(d3.y) * v3;
        }
        for (; e < e1; e++) {
            int2 d = g_edge[e];
            acc += __int_as_float(d.y) * sx[d.x];
        }
        if (RELU) acc = fmaxf(acc, 0.f);
        orow[row] = acc;
    }
}

// ---------------- head weight pre-combine ----------------
__global__ void wcomb_kernel(const float* __restrict__ We, const float* __restrict__ be,
                             const float* __restrict__ Wf, const float* __restrict__ bf)
{
    int t = blockIdx.x * blockDim.x + threadIdx.x;
    if (t < CC * CC) {
        int i = t / CC, c = t % CC;
        float s = 0.f;
        for (int k = 0; k < HH; k++) s += We[i * HH + k] * Wf[k * CC + c];
        g_Wc[t] = s;
    }
    if (t < CC) {
        float s = bf[t];
        for (int k = 0; k < HH; k++) s += be[k] * Wf[k * CC + t];
        g_cbias[t] = s;
    }
}

// ---------------- fused head: logits = y@Wc + h@Wf_bot + cbias ; softmax ----------------
// h is feature-major (hT[k][node]).
__global__ __launch_bounds__(128) void head_kernel(
    const float* __restrict__ hT, const float* __restrict__ yin,
    const float* __restrict__ Wf, float* __restrict__ out, int n)
{
    __shared__ float sWfb[HH * CC];
    __shared__ float sWc[CC * CC];
    __shared__ float sh[32 * 129];
    __shared__ float sl[32 * CC];
    __shared__ float smax[32], sinv[32];
    int tid = threadIdx.x;
    int r0 = blockIdx.x * 32;
    int rows = min(32, n - r0);

    for (int i = tid; i < HH * CC; i += 128) sWfb[i] = Wf[HH * CC + i];
    for (int i = tid; i < CC * CC; i += 128) sWc[i] = g_Wc[i];
    for (int i = tid; i < 32 * HH; i += 128) {
        int k = i >> 5, r = i & 31;
        if (r < rows) sh[r * 129 + k] = hT[(size_t)k * NP + r0 + r];
    }
    __syncthreads();

    int r = tid >> 2, q = tid & 3, c0 = q * 10;
    if (r < rows) {
        float acc[10];
        #pragma unroll
        for (int j = 0; j < 10; j++) acc[j] = g_cbias[c0 + j];
        for (int k = 0; k < HH; k++) {
            float hv = sh[r * 129 + k];
            #pragma unroll
            for (int j = 0; j < 10; j++) acc[j] += hv * sWfb[k * CC + c0 + j];
        }
        const float* yr = yin + (size_t)(r0 + r) * CC;
        for (int k = 0; k < CC; k++) {
            float yv = yr[k];
            #pragma unroll
            for (int j = 0; j < 10; j++) acc[j] += yv * sWc[k * CC + c0 + j];
        }
        #pragma unroll
        for (int j = 0; j < 10; j++) sl[r * CC + c0 + j] = acc[j];
    }
    __syncthreads();
    if (tid < 32 && tid < rows) {
        float m = -1e30f;
        for (int c = 0; c < CC; c++) m = fmaxf(m, sl[tid * CC + c]);
        float s = 0.f;
        for (int c = 0; c < CC; c++) s += __expf(sl[tid * CC + c] - m);
        smax[tid] = m;
        sinv[tid] = 1.0f / s;
    }
    __syncthreads();
    int tot = rows * CC;
    for (int i = tid; i < tot; i += 128) {
        int rr = i / CC;
        out[(size_t)r0 * CC + i] = __expf(sl[i] - smax[rr]) * sinv[rr];
    }
}

// ---------------- launch ----------------
#define SPMM_SMEM (NN * 4)   // 200000 B < 227KB cap

extern "C" void kernel_launch(void* const* d_in, const int* in_sizes, int n_in,
                              void* d_out, int out_size)
{
    const float* features = (const float*)d_in[0];
    const int*   src      = (const int*)  d_in[1];
    const int*   dst      = (const int*)  d_in[2];
    const float* ew       = (const float*)d_in[3];
    const float* y        = (const float*)d_in[4];
    const float* W1       = (const float*)d_in[5];
    const float* b1       = (const float*)d_in[6];
    const float* W2       = (const float*)d_in[7];
    const float* b2       = (const float*)d_in[8];
    const float* We       = (const float*)d_in[9];
    const float* be       = (const float*)d_in[10];
    const float* Wf       = (const float*)d_in[11];
    const float* bf       = (const float*)d_in[12];
    float* out = (float*)d_out;

    int n = in_sizes[0] / FIN;     // 50000
    int e = in_sizes[1];           // 1600000

    // opt-in to >48KB dynamic smem (not stream-ordered; capture-safe)
    cudaFuncSetAttribute(spmmT_kernel<true>,  cudaFuncAttributeMaxDynamicSharedMemorySize, SPMM_SMEM);
    cudaFuncSetAttribute(spmmT_kernel<false>, cudaFuncAttributeMaxDynamicSharedMemorySize, SPMM_SMEM);

    int edgeBlocks = (e + 255) / 256;
    dim3 gemmGrid(NP / GBM, HH / GBN);   // 391 x 2

    hist_kernel<<<edgeBlocks, 256>>>(dst, e);                            // 1
    scan_kernel<<<1, 1024>>>(n);                                         // 2 (re-zeroes g_deg)
    scatter_kernel<<<edgeBlocks, 256>>>(src, dst, ew, e);                // 3
    // PROBE (profiled slot 4): real addresses — CSR fully valid here; x values
    // are stale/zero but timing-equivalent. Output overwritten at slot 6.
    spmmT_kernel<true><<<HH, 1024, SPMM_SMEM>>>(g_xT, g_hT, b1, n);      // 4  <-- profiled
    gemmT_kernel<true,  false><<<gemmGrid, 256>>>(features, W1, g_xT, n, FIN); // 5
    spmmT_kernel<true><<<HH, 1024, SPMM_SMEM>>>(g_xT, g_hT, b1, n);      // 6
    gemmT_kernel<false, true ><<<gemmGrid, 256>>>(g_hT, W2, g_xT, n, HH);      // 7
    spmmT_kernel<false><<<HH, 1024, SPMM_SMEM>>>(g_xT, g_hT, b2, n);     // 8
    wcomb_kernel<<<7, 256>>>(We, be, Wf, bf);                            // 9
    head_kernel<<<(n + 31) / 32, 128>>>(g_hT, y, Wf, out, n);            // 10
}